// round 10
// baseline (speedup 1.0000x reference)
#include <cuda_runtime.h>
#include <cuda_bf16.h>
#include <cstdint>
#include <cstddef>

#define B_ 64
#define S_ 512
#define I_ 768
#define H_ 512
#define G_ 2048            // 4*H
#define M_ 32768           // B*S
#define NBLK 128
#define STEP_THREADS 512

// ---------------- device scratch (no allocations allowed) ----------------
// xp: gate-interleaved input projection [dir][m][u*4+g], g in {i,f,g,o}
__device__ __align__(16) float g_xp[2][(size_t)M_ * G_];        // 512 MB
// Wh packed for the step kernel: [dir][ub][kp][u_off][8]
//   8 floats = {wi[2kp],wi[2kp+1], wf.., wg.., wo..}
__device__ __align__(16) float g_wt2[2][64][256][8][8];         // 8 MB
// hidden state ping-pong: [parity][dir] as float4[kp][bp]:
//   {h[2kp][2bp], h[2kp+1][2bp], h[2kp][2bp+1], h[2kp+1][2bp+1]}
__device__ __align__(16) float g_h[2][2][H_ * B_];
// per-direction grid barrier counters (monotonic within one launch)
__device__ unsigned int g_barD[2];

// ---------------- helpers ----------------
__device__ __forceinline__ unsigned long long splat2(float v) {
    unsigned long long r;
    asm("mov.b64 %0, {%1, %1};" : "=l"(r) : "f"(v));
    return r;
}
__device__ __forceinline__ void fma2(unsigned long long& acc,
                                     unsigned long long a, unsigned long long b) {
    asm("fma.rn.f32x2 %0, %1, %2, %0;" : "+l"(acc) : "l"(a), "l"(b));
}
__device__ __forceinline__ float red2(unsigned long long a) {
    float2 v = *(float2*)&a;
    return v.x + v.y;
}
__device__ __forceinline__ float red2x2(unsigned long long a, unsigned long long b) {
    float2 u = *(float2*)&a;
    float2 v = *(float2*)&b;
    return (u.x + v.x) + (u.y + v.y);
}
__device__ __forceinline__ float fast_rcp(float x) {
    float r;
    asm("rcp.approx.f32 %0, %1;" : "=f"(r) : "f"(x));
    return r;
}
__device__ __forceinline__ float fast_sig(float x) {
    return fast_rcp(1.0f + __expf(-x));          // ex2.approx + rcp.approx, ~1e-7 rel
}
__device__ __forceinline__ float fast_tanh(float x) {
    return 1.0f - 2.0f * fast_rcp(1.0f + __expf(2.0f * x));   // safe at +-inf
}

// ---------------- prep: reset barriers, zero h, build packed Wh ----------------
__global__ void prep_kernel(const float* __restrict__ Wh_f,
                            const float* __restrict__ Wh_b) {
    int idx = blockIdx.x * blockDim.x + threadIdx.x;
    if (idx < 2 * H_ * G_) {               // 2,097,152
        int d = idx >> 20;
        int r = idx & 0xFFFFF;
        int k = r >> 11;                   // 0..511
        int n = r & 2047;                  // source column: g*512 + u
        int g = n >> 9;
        int u = n & 511;
        const float* __restrict__ Wh = d ? Wh_b : Wh_f;
        size_t dst = ((((size_t)d * 64 + (u >> 3)) * 256 + (k >> 1)) * 8
                      + (u & 7)) * 8 + (g << 1) + (k & 1);
        ((float*)g_wt2)[dst] = Wh[(size_t)k * G_ + n];
    }
    if (idx < 2 * 2 * H_ * B_) {           // zero both parities, both dirs
        ((float*)g_h)[idx] = 0.0f;
    }
    if (idx == 0) { g_barD[0] = 0u; g_barD[1] = 0u; }
}

// ---------------- projection GEMM: xp = x @ Wi + bi + bh (both dirs) ----------------
#define BM 128
#define BN 128
#define BK 16

__global__ __launch_bounds__(256) void proj_kernel(
    const float* __restrict__ x,
    const float* __restrict__ Wi_f, const float* __restrict__ bi_f,
    const float* __restrict__ bh_f,
    const float* __restrict__ Wi_b, const float* __restrict__ bi_b,
    const float* __restrict__ bh_b)
{
    __shared__ float As[BK][BM];   // transposed: As[k][m]
    __shared__ float Bs[BK][BN];   // Bs[k][n]

    const int d  = blockIdx.z;
    const float* __restrict__ Wi = d ? Wi_b : Wi_f;
    const float* __restrict__ bi = d ? bi_b : bi_f;
    const float* __restrict__ bh = d ? bh_b : bh_f;

    const int mb = blockIdx.y;
    const int nb = blockIdx.x;
    const int tid = threadIdx.x;
    const int tx = tid & 15;
    const int ty = tid >> 4;

    unsigned long long acc[4][8];
#pragma unroll
    for (int p = 0; p < 4; p++)
#pragma unroll
        for (int c = 0; c < 8; c++) acc[p][c] = 0ULL;

    const int arow  = tid >> 2;
    const int acol4 = tid & 3;
    const float* __restrict__ xg = x + (size_t)(mb * BM) * I_;
    const float* __restrict__ wg = Wi + (size_t)(nb * BN);

    for (int kc = 0; kc < I_; kc += BK) {
#pragma unroll
        for (int j = 0; j < 2; j++) {
            int r = arow + j * 64;
            float4 v = *(const float4*)(xg + (size_t)r * I_ + kc + acol4 * 4);
            As[acol4 * 4 + 0][r] = v.x;
            As[acol4 * 4 + 1][r] = v.y;
            As[acol4 * 4 + 2][r] = v.z;
            As[acol4 * 4 + 3][r] = v.w;
        }
#pragma unroll
        for (int j = 0; j < 2; j++) {
            int idx = j * 256 + tid;
            int r = idx >> 5, c4 = idx & 31;
            float4 v = *(const float4*)(wg + (size_t)(kc + r) * G_ + c4 * 4);
            *(float4*)&Bs[r][c4 * 4] = v;
        }
        __syncthreads();

#pragma unroll
        for (int k = 0; k < BK; k++) {
            unsigned long long a[4];
#pragma unroll
            for (int p = 0; p < 4; p++)
                a[p] = *(const unsigned long long*)&As[k][ty * 8 + 2 * p];
            float4 bv0 = *(const float4*)&Bs[k][tx * 8];
            float4 bv1 = *(const float4*)&Bs[k][tx * 8 + 4];
            float bcols[8] = {bv0.x, bv0.y, bv0.z, bv0.w,
                              bv1.x, bv1.y, bv1.z, bv1.w};
#pragma unroll
            for (int c = 0; c < 8; c++) {
                unsigned long long bs = splat2(bcols[c]);
#pragma unroll
                for (int p = 0; p < 4; p++) fma2(acc[p][c], a[p], bs);
            }
        }
        __syncthreads();
    }

    float* __restrict__ xpd = g_xp[d];
    const int m0 = mb * BM + ty * 8;
    const int n0 = nb * BN + tx * 8;
#pragma unroll
    for (int c = 0; c < 8; c++) {
        int col  = n0 + c;
        float bias = bi[col] + bh[col];
        int u = col & 511;
        int g = col >> 9;
        size_t off = (size_t)(u * 4 + g);
#pragma unroll
        for (int p = 0; p < 4; p++) {
            float2 v = *(float2*)&acc[p][c];
            xpd[(size_t)(m0 + 2 * p)     * G_ + off] = v.x + bias;
            xpd[(size_t)(m0 + 2 * p + 1) * G_ + off] = v.y + bias;
        }
    }
}

// ---------------- persistent BiLSTM recurrence ----------------
// 128 CTAs (2 dirs x 64 unit-blocks of 8 units), 512 threads.
// Thread = (k-half, unit, batch-pair); k-pair f32x2 accumulators.
// smem: h 128K | w 64K | red 20K | out_sm 2K | hstage 2K = 216K.
#define SM_H    0
#define SM_W    32768
#define SM_RED  49152          // ulonglong2[256][5] (padded)
#define SM_OUT  54272          // float[64][8]
#define SM_HST  54784          // float[512]
#define SM_FLOATS 55296        // * 4 = 221184 bytes

__global__ __launch_bounds__(STEP_THREADS, 1) void lstm_persist(
    const float* __restrict__ sent, float* __restrict__ out)
{
    extern __shared__ float sm[];
    float* h_sm     = sm + SM_H;
    float* w_sm     = sm + SM_W;
    ulonglong2* red = (ulonglong2*)(sm + SM_RED);
    float* out_sm   = sm + SM_OUT;
    float* hstage   = sm + SM_HST;

    const int blk = blockIdx.x;
    const int d   = blk >> 6;
    const int ub  = blk & 63;
    const int tid = threadIdx.x;
    const int kh  = tid >> 8;            // k-half
    const int r   = tid & 255;
    const int warp_r = r >> 5;
    const int lane   = tid & 31;
    const int u_off = (warp_r & 1) * 4 + (lane >> 3);   // 0..7
    const int bp    = (warp_r >> 1) * 8 + (lane & 7);   // 0..31
    const int u  = ub * 8 + u_off;
    const int b0 = bp * 2, b1 = b0 + 1;

    // stage Wh slice once (64 KB)
    {
        const float4* wp4 = (const float4*)&g_wt2[d][ub][0][0][0];
        float4* ws4 = (float4*)w_sm;
#pragma unroll
        for (int i = 0; i < 8; i++) ws4[i * 512 + tid] = wp4[i * 512 + tid];
    }

    float c0 = 0.0f, c1 = 0.0f;
    const float* __restrict__ xpd = g_xp[d];

    for (int s = 0; s < S_; s++) {
        const int t = d ? (S_ - 1 - s) : s;
        const int p = s & 1;

        // xp + sentiment prefetch (kh0 warps only; overlaps h staging)
        float4 xq0, xq1; float st0 = 0.f, st1 = 0.f;
        if (kh == 0) {
            xq0 = __ldcs((const float4*)(xpd + ((size_t)b0 * S_ + t) * G_ + (size_t)u * 4));
            xq1 = __ldcs((const float4*)(xpd + ((size_t)b1 * S_ + t) * G_ + (size_t)u * 4));
            st0 = __ldg(sent + b0 * S_ + t);
            st1 = __ldg(sent + b1 * S_ + t);
        }

        // stage h_prev (128 KB, L2-coherent)
        {
            const float4* hp4 = (const float4*)g_h[p][d];
            float4* hs4 = (float4*)h_sm;
#pragma unroll 16
            for (int i = 0; i < 16; i++)
                hs4[i * 512 + tid] = __ldcg(hp4 + i * 512 + tid);
        }
        __syncthreads();

        // GEMM half: 4 gates x 2 batches over 128 k-pairs, pointer-increment
        unsigned long long ai0 = 0, af0 = 0, ag0 = 0, ao0 = 0;
        unsigned long long ai1 = 0, af1 = 0, ag1 = 0, ao1 = 0;
        {
            const ulonglong2* __restrict__ hq =
                (const ulonglong2*)h_sm + (kh << 7) * 32 + bp;
            const ulonglong2* __restrict__ wq =
                (const ulonglong2*)w_sm + (kh << 7) * 16 + (u_off << 1);
#pragma unroll 8
            for (int kp = 0; kp < 128; kp++) {
                ulonglong2 h2 = hq[0];
                ulonglong2 wa = wq[0];
                ulonglong2 wb = wq[1];
                hq += 32; wq += 16;
                fma2(ai0, h2.x, wa.x);
                fma2(af0, h2.x, wa.y);
                fma2(ag0, h2.x, wb.x);
                fma2(ao0, h2.x, wb.y);
                fma2(ai1, h2.y, wa.x);
                fma2(af1, h2.y, wa.y);
                fma2(ag1, h2.y, wb.x);
                fma2(ao1, h2.y, wb.y);
            }
        }

        // cross-half reduction
        if (kh == 1) {
            ulonglong2* rp = red + r * 5;
            rp[0] = make_ulonglong2(ai0, af0);
            rp[1] = make_ulonglong2(ag0, ao0);
            rp[2] = make_ulonglong2(ai1, af1);
            rp[3] = make_ulonglong2(ag1, ao1);
        }
        __syncthreads();

        if (kh == 0) {
            const ulonglong2* rp = red + r * 5;
            ulonglong2 q0 = rp[0], q1 = rp[1], q2 = rp[2], q3 = rp[3];
            float gi0 = red2x2(ai0, q0.x) + xq0.x;
            float gf0 = red2x2(af0, q0.y) + xq0.y;
            float gg0 = red2x2(ag0, q1.x) + xq0.z;
            float go0 = red2x2(ao0, q1.y) + xq0.w;
            float gi1 = red2x2(ai1, q2.x) + xq1.x;
            float gf1 = red2x2(af1, q2.y) + xq1.y;
            float gg1 = red2x2(ag1, q3.x) + xq1.z;
            float go1 = red2x2(ao1, q3.y) + xq1.w;

            float i0 = fast_sig(gi0) * st0;
            float f0 = fast_sig(gf0) * (1.0f + st0);
            float o0 = fast_sig(go0);
            c0 = f0 * c0 + i0 * fast_tanh(gg0);
            float h0 = o0 * fast_tanh(c0);

            float i1 = fast_sig(gi1) * st1;
            float f1 = fast_sig(gf1) * (1.0f + st1);
            float o1 = fast_sig(go1);
            c1 = f1 * c1 + i1 * fast_tanh(gg1);
            float h1 = o1 * fast_tanh(c1);

            // gather into smem for coalesced global stores
            int hidx = ((u_off >> 1) * 32 + bp) * 4 + (u_off & 1);
            hstage[hidx]     = h0;
            hstage[hidx + 2] = h1;
            out_sm[b0 * 8 + u_off] = h0;
            out_sm[b1 * 8 + u_off] = h1;
        }
        __syncthreads();

        // coalesced float4 stores: h ping-pong slice (2 KB) + output tile (2 KB)
        if (tid < 128) {
            float4 v = *(float4*)&hstage[tid * 4];
            __stcg((float4*)g_h[p ^ 1][d] + ub * 128 + tid, v);
        } else if (tid < 256) {
            int i = tid - 128;
            int b = i >> 1, hf = i & 1;
            float4 v = *(float4*)&out_sm[b * 8 + hf * 4];
            *(float4*)(out + ((size_t)b * S_ + t) * (size_t)(2 * H_)
                           + (size_t)d * H_ + ub * 8 + hf * 4) = v;
        }

        if (s == S_ - 1) break;

        // per-direction grid barrier
        __threadfence();
        __syncthreads();
        if (tid == 0) {
            atomicAdd(&g_barD[d], 1u);
            const unsigned int target = (unsigned int)(s + 1) * 64u;
            while (*((volatile unsigned int*)&g_barD[d]) < target) { }
        }
        __syncthreads();
    }
}

// ---------------- launch ----------------
extern "C" void kernel_launch(void* const* d_in, const int* in_sizes, int n_in,
                              void* d_out, int out_size) {
    const float* x    = (const float*)d_in[0];
    const float* sent = (const float*)d_in[1];
    const float* Wi_f = (const float*)d_in[2];
    const float* bi_f = (const float*)d_in[3];
    const float* Wh_f = (const float*)d_in[4];
    const float* bh_f = (const float*)d_in[5];
    const float* Wi_b = (const float*)d_in[6];
    const float* bi_b = (const float*)d_in[7];
    const float* Wh_b = (const float*)d_in[8];
    const float* bh_b = (const float*)d_in[9];
    float* out = (float*)d_out;

    cudaFuncSetAttribute(lstm_persist,
                         cudaFuncAttributeMaxDynamicSharedMemorySize,
                         SM_FLOATS * 4);

    // reset barriers, zero h, build packed Wh (every launch: replay-safe)
    prep_kernel<<<8192, 256>>>(Wh_f, Wh_b);

    // input projection for both directions
    dim3 pg(G_ / BN, M_ / BM, 2);
    proj_kernel<<<pg, 256>>>(x, Wi_f, bi_f, bh_f, Wi_b, bi_b, bh_b);

    // whole recurrence in one persistent launch
    lstm_persist<<<NBLK, STEP_THREADS, SM_FLOATS * 4>>>(sent, out);
}

// round 11
// speedup vs baseline: 2.0966x; 2.0966x over previous
#include <cuda_runtime.h>
#include <cuda_bf16.h>
#include <cstdint>
#include <cstddef>

#define B_ 64
#define S_ 512
#define I_ 768
#define H_ 512
#define G_ 2048            // 4*H
#define M_ 32768           // B*S
#define NBLK 128

// ---------------- device scratch (no allocations allowed) ----------------
// xp: gate-interleaved input projection [dir][m][u*4+g], g in {i,f,g,o}
__device__ __align__(16) float g_xp[2][(size_t)M_ * G_];        // 512 MB
// bf16 splits of x and Wi
__device__ __align__(16) __nv_bfloat16 g_xh[(size_t)M_ * I_];   // 48 MB
__device__ __align__(16) __nv_bfloat16 g_xl[(size_t)M_ * I_];   // 48 MB
__device__ __align__(16) __nv_bfloat16 g_wh[2][(size_t)I_ * G_];// 6.3 MB
__device__ __align__(16) __nv_bfloat16 g_wl[2][(size_t)I_ * G_];
// Wh packed for the step kernel: [dir][ub][kp][u_off][8]
__device__ __align__(16) float g_wt2[2][64][256][8][8];         // 8 MB
// hidden state ping-pong: [parity][dir] as float4[kp][bp]
__device__ __align__(16) float g_h[2][2][H_ * B_];
// grid barrier counter (monotonic within one launch; reset by prep)
__device__ unsigned int g_bar;

// ---------------- helpers ----------------
__device__ __forceinline__ unsigned long long splat2(float v) {
    unsigned long long r;
    asm("mov.b64 %0, {%1, %1};" : "=l"(r) : "f"(v));
    return r;
}
__device__ __forceinline__ void fma2(unsigned long long& acc,
                                     unsigned long long a, unsigned long long b) {
    asm("fma.rn.f32x2 %0, %1, %2, %0;" : "+l"(acc) : "l"(a), "l"(b));
}
__device__ __forceinline__ float red2(unsigned long long a) {
    float2 v = *(float2*)&a;
    return v.x + v.y;
}
__device__ __forceinline__ float fast_rcp(float x) {
    float r;
    asm("rcp.approx.f32 %0, %1;" : "=f"(r) : "f"(x));
    return r;
}
__device__ __forceinline__ float fast_sig(float x) {
    return fast_rcp(1.0f + __expf(-x));
}
__device__ __forceinline__ float fast_tanh(float x) {
    return 1.0f - 2.0f * fast_rcp(1.0f + __expf(2.0f * x));
}
__device__ __forceinline__ uint32_t sm_u32(const void* p) {
    return (uint32_t)__cvta_generic_to_shared(p);
}
__device__ __forceinline__ void ldsm4(uint32_t addr, uint32_t& r0, uint32_t& r1,
                                      uint32_t& r2, uint32_t& r3) {
    asm volatile("ldmatrix.sync.aligned.m8n8.x4.shared.b16 {%0,%1,%2,%3}, [%4];"
                 : "=r"(r0), "=r"(r1), "=r"(r2), "=r"(r3) : "r"(addr));
}
__device__ __forceinline__ void ldsm4t(uint32_t addr, uint32_t& r0, uint32_t& r1,
                                       uint32_t& r2, uint32_t& r3) {
    asm volatile("ldmatrix.sync.aligned.m8n8.x4.trans.shared.b16 {%0,%1,%2,%3}, [%4];"
                 : "=r"(r0), "=r"(r1), "=r"(r2), "=r"(r3) : "r"(addr));
}
__device__ __forceinline__ void mma16816(float* d, uint32_t a0, uint32_t a1,
                                         uint32_t a2, uint32_t a3,
                                         uint32_t b0, uint32_t b1) {
    asm volatile(
        "mma.sync.aligned.m16n8k16.row.col.f32.bf16.bf16.f32 "
        "{%0,%1,%2,%3}, {%4,%5,%6,%7}, {%8,%9}, {%0,%1,%2,%3};"
        : "+f"(d[0]), "+f"(d[1]), "+f"(d[2]), "+f"(d[3])
        : "r"(a0), "r"(a1), "r"(a2), "r"(a3), "r"(b0), "r"(b1));
}

// ---------------- prep: reset barrier, zero h, build packed Wh ----------------
__global__ void prep_kernel(const float* __restrict__ Wh_f,
                            const float* __restrict__ Wh_b) {
    int idx = blockIdx.x * blockDim.x + threadIdx.x;
    if (idx < 2 * H_ * G_) {
        int d = idx >> 20;
        int r = idx & 0xFFFFF;
        int k = r >> 11;
        int n = r & 2047;
        int g = n >> 9;
        int u = n & 511;
        const float* __restrict__ Wh = d ? Wh_b : Wh_f;
        size_t dst = ((((size_t)d * 64 + (u >> 3)) * 256 + (k >> 1)) * 8
                      + (u & 7)) * 8 + (g << 1) + (k & 1);
        ((float*)g_wt2)[dst] = Wh[(size_t)k * G_ + n];
    }
    if (idx < 2 * 2 * H_ * B_) {
        ((float*)g_h)[idx] = 0.0f;
    }
    if (idx == 0) g_bar = 0u;
}

// ---------------- bf16 split conversions ----------------
__global__ void conv_x_kernel(const float* __restrict__ x) {
    size_t idx = (size_t)blockIdx.x * blockDim.x + threadIdx.x;
    if (idx < (size_t)M_ * I_) {
        float v = x[idx];
        __nv_bfloat16 h = __float2bfloat16(v);
        g_xh[idx] = h;
        g_xl[idx] = __float2bfloat16(v - __bfloat162float(h));
    }
}
__global__ void conv_w_kernel(const float* __restrict__ Wi_f,
                              const float* __restrict__ Wi_b) {
    size_t idx = (size_t)blockIdx.x * blockDim.x + threadIdx.x;
    const size_t n1 = (size_t)I_ * G_;
    if (idx < 2 * n1) {
        int d = idx >= n1;
        size_t r = d ? idx - n1 : idx;
        float v = (d ? Wi_b : Wi_f)[r];
        __nv_bfloat16 h = __float2bfloat16(v);
        g_wh[d][r] = h;
        g_wl[d][r] = __float2bfloat16(v - __bfloat162float(h));
    }
}

// ---------------- tensor-core projection: xp = x@Wi + bi + bh (3-term bf16) ----------------
// Block tile 128x128, BK=64. 8 warps: warp grid 4(m) x 2(n), warp tile 32x64.
// smem 64 KB: A_hi | A_lo (128x64 bf16, 8 chunks/row, XOR swizzle)
//             B_hi | B_lo (64x128 bf16, 16 chunks/row, XOR swizzle)
#define PA_HI 0
#define PA_LO 16384
#define PB_HI 32768
#define PB_LO 49152

__global__ __launch_bounds__(256) void proj_mma_kernel(
    const float* __restrict__ bi_f, const float* __restrict__ bh_f,
    const float* __restrict__ bi_b, const float* __restrict__ bh_b)
{
    extern __shared__ char smem[];
    const uint32_t smem_b = sm_u32(smem);

    const int d  = blockIdx.z;
    const int mb = blockIdx.y;     // 0..255
    const int nb = blockIdx.x;     // 0..15
    const int tid = threadIdx.x;
    const int warp = tid >> 5, lane = tid & 31;
    const int warp_m = (warp >> 1) * 32;
    const int warp_n = (warp & 1) * 64;

    const __nv_bfloat16* __restrict__ wh = g_wh[d];
    const __nv_bfloat16* __restrict__ wl = g_wl[d];
    const float* __restrict__ bi = d ? bi_b : bi_f;
    const float* __restrict__ bh = d ? bh_b : bh_f;

    float acc[2][8][4];
#pragma unroll
    for (int fr = 0; fr < 2; fr++)
#pragma unroll
        for (int nf = 0; nf < 8; nf++)
#pragma unroll
            for (int r = 0; r < 4; r++) acc[fr][nf][r] = 0.0f;

    for (int kc = 0; kc < I_; kc += 64) {
        if (kc) __syncthreads();
        // stage A (x_hi, x_lo): 128 rows x 8 chunks of 16B
#pragma unroll
        for (int i = 0; i < 4; i++) {
            int id = i * 256 + tid;
            int row = id >> 3, c = id & 7;
            size_t ga = (size_t)(mb * 128 + row) * I_ + kc + c * 8;
            int phys = row * 8 + (c ^ (row & 7));
            *((uint4*)(smem + PA_HI) + phys) = *(const uint4*)(g_xh + ga);
            *((uint4*)(smem + PA_LO) + phys) = *(const uint4*)(g_xl + ga);
        }
        // stage B (W_hi, W_lo): 64 rows x 16 chunks of 16B
#pragma unroll
        for (int i = 0; i < 4; i++) {
            int id = i * 256 + tid;
            int row = id >> 4, c = id & 15;
            size_t gb = (size_t)(kc + row) * G_ + nb * 128 + c * 8;
            int phys = row * 16 + (c ^ (row & 7));
            *((uint4*)(smem + PB_HI) + phys) = *(const uint4*)(wh + gb);
            *((uint4*)(smem + PB_LO) + phys) = *(const uint4*)(wl + gb);
        }
        __syncthreads();

#pragma unroll
        for (int k16 = 0; k16 < 64; k16 += 16) {
            // A fragments: rows warp_m..warp_m+31, k16..k16+15
            uint32_t ah[2][4], al[2][4];
#pragma unroll
            for (int fr = 0; fr < 2; fr++) {
                int row = warp_m + fr * 16 + (lane & 15);
                int cb = (k16 >> 3) + (lane >> 4);
                uint32_t off = (uint32_t)(row * 8 + (cb ^ (row & 7))) * 16;
                ldsm4(smem_b + PA_HI + off, ah[fr][0], ah[fr][1], ah[fr][2], ah[fr][3]);
                ldsm4(smem_b + PA_LO + off, al[fr][0], al[fr][1], al[fr][2], al[fr][3]);
            }
#pragma unroll
            for (int ng = 0; ng < 4; ng++) {
                // B fragment pair (two adjacent n8 chunks) via x4.trans
                int row = k16 + ((lane >> 3) & 1) * 8 + (lane & 7);
                int c0 = (warp_n >> 3) + ng * 2 + (lane >> 4);
                uint32_t off = (uint32_t)(row * 16 + (c0 ^ (row & 7))) * 16;
                uint32_t bh0, bh1, bh2, bh3, bl0, bl1, bl2, bl3;
                ldsm4t(smem_b + PB_HI + off, bh0, bh1, bh2, bh3);
                ldsm4t(smem_b + PB_LO + off, bl0, bl1, bl2, bl3);
                int nf0 = ng * 2, nf1 = ng * 2 + 1;
#pragma unroll
                for (int fr = 0; fr < 2; fr++) {
                    // hi*hi
                    mma16816(acc[fr][nf0], ah[fr][0], ah[fr][1], ah[fr][2], ah[fr][3], bh0, bh1);
                    mma16816(acc[fr][nf1], ah[fr][0], ah[fr][1], ah[fr][2], ah[fr][3], bh2, bh3);
                    // hi*lo
                    mma16816(acc[fr][nf0], ah[fr][0], ah[fr][1], ah[fr][2], ah[fr][3], bl0, bl1);
                    mma16816(acc[fr][nf1], ah[fr][0], ah[fr][1], ah[fr][2], ah[fr][3], bl2, bl3);
                    // lo*hi
                    mma16816(acc[fr][nf0], al[fr][0], al[fr][1], al[fr][2], al[fr][3], bh0, bh1);
                    mma16816(acc[fr][nf1], al[fr][0], al[fr][1], al[fr][2], al[fr][3], bh2, bh3);
                }
            }
        }
    }

    // epilogue: bias + gate-interleaved store to g_xp[d][m][u*4+g]
    float* __restrict__ xpd = g_xp[d];
#pragma unroll
    for (int nf = 0; nf < 8; nf++) {
        int n0 = nb * 128 + warp_n + nf * 8 + (lane & 3) * 2;
        float bias0 = bi[n0] + bh[n0];
        float bias1 = bi[n0 + 1] + bh[n0 + 1];
        size_t off0 = (size_t)((n0 & 511) * 4 + (n0 >> 9));
        size_t off1 = (size_t)(((n0 + 1) & 511) * 4 + ((n0 + 1) >> 9));
#pragma unroll
        for (int fr = 0; fr < 2; fr++) {
            int m0 = mb * 128 + warp_m + fr * 16 + (lane >> 2);
            xpd[(size_t)m0       * G_ + off0] = acc[fr][nf][0] + bias0;
            xpd[(size_t)m0       * G_ + off1] = acc[fr][nf][1] + bias1;
            xpd[(size_t)(m0 + 8) * G_ + off0] = acc[fr][nf][2] + bias0;
            xpd[(size_t)(m0 + 8) * G_ + off1] = acc[fr][nf][3] + bias1;
        }
    }
}

// ---------------- persistent BiLSTM recurrence (R8 structure, MUFU act) ----------------
__global__ __launch_bounds__(256, 1) void lstm_persist(
    const float* __restrict__ sent, float* __restrict__ out)
{
    extern __shared__ float sm[];
    float* h_sm = sm;            // float4[256 kp][32 bp] = 128 KB
    float* w_sm = sm + 32768;    // float [256 kp][8 u_off][8] = 64 KB

    const int blk = blockIdx.x;
    const int d   = blk >> 6;
    const int ub  = blk & 63;
    const int tid = threadIdx.x;
    const int warp = tid >> 5, lane = tid & 31;
    const int u_off = (warp & 1) * 4 + (lane >> 3);
    const int bp    = (warp >> 1) * 8 + (lane & 7);
    const int u  = ub * 8 + u_off;
    const int b0 = bp * 2, b1 = b0 + 1;

    {
        const float4* wp4 = (const float4*)&g_wt2[d][ub][0][0][0];
        float4* ws4 = (float4*)w_sm;
#pragma unroll
        for (int i = 0; i < 16; i++) ws4[i * 256 + tid] = wp4[i * 256 + tid];
    }

    float c0 = 0.0f, c1 = 0.0f;
    const float* __restrict__ xpd = g_xp[d];
    const ulonglong2* __restrict__ wl2 = (const ulonglong2*)w_sm + u_off * 2;
    const ulonglong2* __restrict__ hl2 = (const ulonglong2*)h_sm + bp;

    for (int s = 0; s < S_; s++) {
        const int t = d ? (S_ - 1 - s) : s;
        const int p = s & 1;

        float4 xq0 = __ldcs((const float4*)(xpd + ((size_t)b0 * S_ + t) * G_ + (size_t)u * 4));
        float4 xq1 = __ldcs((const float4*)(xpd + ((size_t)b1 * S_ + t) * G_ + (size_t)u * 4));
        float st0 = __ldg(sent + b0 * S_ + t);
        float st1 = __ldg(sent + b1 * S_ + t);

        {
            const float4* hp4 = (const float4*)g_h[p][d];
            float4* hs4 = (float4*)h_sm;
#pragma unroll 8
            for (int i = 0; i < 32; i++)
                hs4[i * 256 + tid] = __ldcg(hp4 + i * 256 + tid);
        }
        __syncthreads();

        unsigned long long ai0 = 0, af0 = 0, ag0 = 0, ao0 = 0;
        unsigned long long ai1 = 0, af1 = 0, ag1 = 0, ao1 = 0;
#pragma unroll 8
        for (int kp = 0; kp < 256; kp++) {
            ulonglong2 h2 = hl2[(size_t)kp * 32];
            ulonglong2 wa = wl2[(size_t)kp * 16];
            ulonglong2 wb = wl2[(size_t)kp * 16 + 1];
            fma2(ai0, h2.x, wa.x);
            fma2(af0, h2.x, wa.y);
            fma2(ag0, h2.x, wb.x);
            fma2(ao0, h2.x, wb.y);
            fma2(ai1, h2.y, wa.x);
            fma2(af1, h2.y, wa.y);
            fma2(ag1, h2.y, wb.x);
            fma2(ao1, h2.y, wb.y);
        }

        float gi0 = red2(ai0) + xq0.x;
        float gf0 = red2(af0) + xq0.y;
        float gg0 = red2(ag0) + xq0.z;
        float go0 = red2(ao0) + xq0.w;
        float i0 = fast_sig(gi0) * st0;
        float f0 = fast_sig(gf0) * (1.0f + st0);
        float o0 = fast_sig(go0);
        c0 = f0 * c0 + i0 * fast_tanh(gg0);
        float h0 = o0 * fast_tanh(c0);

        float gi1 = red2(ai1) + xq1.x;
        float gf1 = red2(af1) + xq1.y;
        float gg1 = red2(ag1) + xq1.z;
        float go1 = red2(ao1) + xq1.w;
        float i1 = fast_sig(gi1) * st1;
        float f1 = fast_sig(gf1) * (1.0f + st1);
        float o1 = fast_sig(go1);
        c1 = f1 * c1 + i1 * fast_tanh(gg1);
        float h1 = o1 * fast_tanh(c1);

        {
            float* hn = g_h[p ^ 1][d];
            int hbase = ((u >> 1) * 32 + bp) * 4 + (u & 1);
            __stcg(hn + hbase,     h0);
            __stcg(hn + hbase + 2, h1);
        }
        __stcs(out + ((size_t)b0 * S_ + t) * (size_t)(2 * H_) + (size_t)d * H_ + u, h0);
        __stcs(out + ((size_t)b1 * S_ + t) * (size_t)(2 * H_) + (size_t)d * H_ + u, h1);

        if (s == S_ - 1) break;
        __threadfence();
        __syncthreads();
        if (tid == 0) {
            atomicAdd(&g_bar, 1u);
            const unsigned int target = (unsigned int)(s + 1) * NBLK;
            while (*((volatile unsigned int*)&g_bar) < target) { }
        }
        __syncthreads();
    }
}

// ---------------- launch ----------------
extern "C" void kernel_launch(void* const* d_in, const int* in_sizes, int n_in,
                              void* d_out, int out_size) {
    const float* x    = (const float*)d_in[0];
    const float* sent = (const float*)d_in[1];
    const float* Wi_f = (const float*)d_in[2];
    const float* bi_f = (const float*)d_in[3];
    const float* Wh_f = (const float*)d_in[4];
    const float* bh_f = (const float*)d_in[5];
    const float* Wi_b = (const float*)d_in[6];
    const float* bi_b = (const float*)d_in[7];
    const float* Wh_b = (const float*)d_in[8];
    const float* bh_b = (const float*)d_in[9];
    float* out = (float*)d_out;

    cudaFuncSetAttribute(lstm_persist,
                         cudaFuncAttributeMaxDynamicSharedMemorySize, 196608);
    cudaFuncSetAttribute(proj_mma_kernel,
                         cudaFuncAttributeMaxDynamicSharedMemorySize, 65536);

    // reset barrier, zero h, pack Wh; build bf16 splits
    prep_kernel<<<8192, 256>>>(Wh_f, Wh_b);
    conv_x_kernel<<<(int)(((size_t)M_ * I_ + 255) / 256), 256>>>(x);
    conv_w_kernel<<<(int)((2 * (size_t)I_ * G_ + 255) / 256), 256>>>(Wi_f, Wi_b);

    // tensor-core input projection, both directions
    dim3 pg(16, 256, 2);
    proj_mma_kernel<<<pg, 256, 65536>>>(bi_f, bh_f, bi_b, bh_b);

    // whole recurrence in one persistent launch
    lstm_persist<<<NBLK, 256, 196608>>>(sent, out);
}

// round 13
// speedup vs baseline: 2.1604x; 1.0305x over previous
#include <cuda_runtime.h>
#include <cuda_bf16.h>
#include <cstdint>
#include <cstddef>

#define B_ 64
#define S_ 512
#define I_ 768
#define H_ 512
#define G_ 2048            // 4*H
#define M_ 32768           // B*S
#define NBLK 128

// ---------------- device scratch (no allocations allowed) ----------------
// xp: gate-interleaved input projection [dir][m][u*4+g], g in {i,f,g,o}
__device__ __align__(16) float g_xp[2][(size_t)M_ * G_];        // 512 MB
// bf16 splits of x and Wi
__device__ __align__(16) __nv_bfloat16 g_xh[(size_t)M_ * I_];   // 48 MB
__device__ __align__(16) __nv_bfloat16 g_xl[(size_t)M_ * I_];   // 48 MB
__device__ __align__(16) __nv_bfloat16 g_wh[2][(size_t)I_ * G_];// 6.3 MB
__device__ __align__(16) __nv_bfloat16 g_wl[2][(size_t)I_ * G_];
// Wh packed for the step kernel: [dir][ub][kp][u_off][8]
__device__ __align__(16) float g_wt2[2][64][256][8][8];         // 8 MB
// hidden state ping-pong: [parity][dir] as float4[kp][bp]
__device__ __align__(16) float g_h[2][2][H_ * B_];
// per-direction grid barrier counters (monotonic within one launch)
__device__ unsigned int g_barD[2];

// ---------------- helpers ----------------
__device__ __forceinline__ unsigned long long splat2(float v) {
    unsigned long long r;
    asm("mov.b64 %0, {%1, %1};" : "=l"(r) : "f"(v));
    return r;
}
__device__ __forceinline__ void fma2(unsigned long long& acc,
                                     unsigned long long a, unsigned long long b) {
    asm("fma.rn.f32x2 %0, %1, %2, %0;" : "+l"(acc) : "l"(a), "l"(b));
}
__device__ __forceinline__ float red2(unsigned long long a) {
    float2 v = *(float2*)&a;
    return v.x + v.y;
}
__device__ __forceinline__ float fast_rcp(float x) {
    float r;
    asm("rcp.approx.f32 %0, %1;" : "=f"(r) : "f"(x));
    return r;
}
__device__ __forceinline__ float fast_sig(float x) {
    return fast_rcp(1.0f + __expf(-x));
}
__device__ __forceinline__ float fast_tanh(float x) {
    return 1.0f - 2.0f * fast_rcp(1.0f + __expf(2.0f * x));
}
__device__ __forceinline__ uint32_t sm_u32(const void* p) {
    return (uint32_t)__cvta_generic_to_shared(p);
}
__device__ __forceinline__ void cp_async16(uint32_t smem_addr, const void* gptr) {
    asm volatile("cp.async.cg.shared.global [%0], [%1], 16;"
                 :: "r"(smem_addr), "l"(gptr));
}
__device__ __forceinline__ void cp_async_wait_all() {
    asm volatile("cp.async.commit_group;\n\tcp.async.wait_group 0;" ::: "memory");
}
__device__ __forceinline__ void bar_release_add(unsigned int* p) {
    asm volatile("red.release.gpu.global.add.u32 [%0], 1;" :: "l"(p) : "memory");
}
__device__ __forceinline__ unsigned int bar_acquire_ld(const unsigned int* p) {
    unsigned int v;
    asm volatile("ld.acquire.gpu.global.u32 %0, [%1];" : "=r"(v) : "l"(p) : "memory");
    return v;
}
__device__ __forceinline__ void ldsm4(uint32_t addr, uint32_t& r0, uint32_t& r1,
                                      uint32_t& r2, uint32_t& r3) {
    asm volatile("ldmatrix.sync.aligned.m8n8.x4.shared.b16 {%0,%1,%2,%3}, [%4];"
                 : "=r"(r0), "=r"(r1), "=r"(r2), "=r"(r3) : "r"(addr));
}
__device__ __forceinline__ void ldsm4t(uint32_t addr, uint32_t& r0, uint32_t& r1,
                                       uint32_t& r2, uint32_t& r3) {
    asm volatile("ldmatrix.sync.aligned.m8n8.x4.trans.shared.b16 {%0,%1,%2,%3}, [%4];"
                 : "=r"(r0), "=r"(r1), "=r"(r2), "=r"(r3) : "r"(addr));
}
__device__ __forceinline__ void mma16816(float* d, uint32_t a0, uint32_t a1,
                                         uint32_t a2, uint32_t a3,
                                         uint32_t b0, uint32_t b1) {
    asm volatile(
        "mma.sync.aligned.m16n8k16.row.col.f32.bf16.bf16.f32 "
        "{%0,%1,%2,%3}, {%4,%5,%6,%7}, {%8,%9}, {%0,%1,%2,%3};"
        : "+f"(d[0]), "+f"(d[1]), "+f"(d[2]), "+f"(d[3])
        : "r"(a0), "r"(a1), "r"(a2), "r"(a3), "r"(b0), "r"(b1));
}

// ---------------- prep: reset barriers, zero h, build packed Wh ----------------
__global__ void prep_kernel(const float* __restrict__ Wh_f,
                            const float* __restrict__ Wh_b) {
    int idx = blockIdx.x * blockDim.x + threadIdx.x;
    if (idx < 2 * H_ * G_) {
        int d = idx >> 20;
        int r = idx & 0xFFFFF;
        int k = r >> 11;
        int n = r & 2047;
        int g = n >> 9;
        int u = n & 511;
        const float* __restrict__ Wh = d ? Wh_b : Wh_f;
        size_t dst = ((((size_t)d * 64 + (u >> 3)) * 256 + (k >> 1)) * 8
                      + (u & 7)) * 8 + (g << 1) + (k & 1);
        ((float*)g_wt2)[dst] = Wh[(size_t)k * G_ + n];
    }
    if (idx < 2 * 2 * H_ * B_) {
        ((float*)g_h)[idx] = 0.0f;
    }
    if (idx == 0) { g_barD[0] = 0u; g_barD[1] = 0u; }
}

// ---------------- bf16 split conversions ----------------
__global__ void conv_x_kernel(const float* __restrict__ x) {
    size_t idx = (size_t)blockIdx.x * blockDim.x + threadIdx.x;
    if (idx < (size_t)M_ * I_) {
        float v = x[idx];
        __nv_bfloat16 h = __float2bfloat16(v);
        g_xh[idx] = h;
        g_xl[idx] = __float2bfloat16(v - __bfloat162float(h));
    }
}
__global__ void conv_w_kernel(const float* __restrict__ Wi_f,
                              const float* __restrict__ Wi_b) {
    size_t idx = (size_t)blockIdx.x * blockDim.x + threadIdx.x;
    const size_t n1 = (size_t)I_ * G_;
    if (idx < 2 * n1) {
        int d = idx >= n1;
        size_t r = d ? idx - n1 : idx;
        float v = (d ? Wi_b : Wi_f)[r];
        __nv_bfloat16 h = __float2bfloat16(v);
        g_wh[d][r] = h;
        g_wl[d][r] = __float2bfloat16(v - __bfloat162float(h));
    }
}

// ---------------- tensor-core projection: xp = x@Wi + bi + bh (3-term bf16) ----------------
#define PA_HI 0
#define PA_LO 16384
#define PB_HI 32768
#define PB_LO 49152

__global__ __launch_bounds__(256) void proj_mma_kernel(
    const float* __restrict__ bi_f, const float* __restrict__ bh_f,
    const float* __restrict__ bi_b, const float* __restrict__ bh_b)
{
    extern __shared__ char smem[];
    const uint32_t smem_b = sm_u32(smem);

    const int d  = blockIdx.z;
    const int mb = blockIdx.y;
    const int nb = blockIdx.x;
    const int tid = threadIdx.x;
    const int warp = tid >> 5, lane = tid & 31;
    const int warp_m = (warp >> 1) * 32;
    const int warp_n = (warp & 1) * 64;

    const __nv_bfloat16* __restrict__ wh = g_wh[d];
    const __nv_bfloat16* __restrict__ wl = g_wl[d];
    const float* __restrict__ bi = d ? bi_b : bi_f;
    const float* __restrict__ bh = d ? bh_b : bh_f;

    float acc[2][8][4];
#pragma unroll
    for (int fr = 0; fr < 2; fr++)
#pragma unroll
        for (int nf = 0; nf < 8; nf++)
#pragma unroll
            for (int r = 0; r < 4; r++) acc[fr][nf][r] = 0.0f;

    for (int kc = 0; kc < I_; kc += 64) {
        if (kc) __syncthreads();
#pragma unroll
        for (int i = 0; i < 4; i++) {
            int id = i * 256 + tid;
            int row = id >> 3, c = id & 7;
            size_t ga = (size_t)(mb * 128 + row) * I_ + kc + c * 8;
            int phys = row * 8 + (c ^ (row & 7));
            *((uint4*)(smem + PA_HI) + phys) = *(const uint4*)(g_xh + ga);
            *((uint4*)(smem + PA_LO) + phys) = *(const uint4*)(g_xl + ga);
        }
#pragma unroll
        for (int i = 0; i < 4; i++) {
            int id = i * 256 + tid;
            int row = id >> 4, c = id & 15;
            size_t gb = (size_t)(kc + row) * G_ + nb * 128 + c * 8;
            int phys = row * 16 + (c ^ (row & 7));
            *((uint4*)(smem + PB_HI) + phys) = *(const uint4*)(wh + gb);
            *((uint4*)(smem + PB_LO) + phys) = *(const uint4*)(wl + gb);
        }
        __syncthreads();

#pragma unroll
        for (int k16 = 0; k16 < 64; k16 += 16) {
            uint32_t ah[2][4], al[2][4];
#pragma unroll
            for (int fr = 0; fr < 2; fr++) {
                int row = warp_m + fr * 16 + (lane & 15);
                int cb = (k16 >> 3) + (lane >> 4);
                uint32_t off = (uint32_t)(row * 8 + (cb ^ (row & 7))) * 16;
                ldsm4(smem_b + PA_HI + off, ah[fr][0], ah[fr][1], ah[fr][2], ah[fr][3]);
                ldsm4(smem_b + PA_LO + off, al[fr][0], al[fr][1], al[fr][2], al[fr][3]);
            }
#pragma unroll
            for (int ng = 0; ng < 4; ng++) {
                int row = k16 + ((lane >> 3) & 1) * 8 + (lane & 7);
                int c0 = (warp_n >> 3) + ng * 2 + (lane >> 4);
                uint32_t off = (uint32_t)(row * 16 + (c0 ^ (row & 7))) * 16;
                uint32_t bh0, bh1, bh2, bh3, bl0, bl1, bl2, bl3;
                ldsm4t(smem_b + PB_HI + off, bh0, bh1, bh2, bh3);
                ldsm4t(smem_b + PB_LO + off, bl0, bl1, bl2, bl3);
                int nf0 = ng * 2, nf1 = ng * 2 + 1;
#pragma unroll
                for (int fr = 0; fr < 2; fr++) {
                    mma16816(acc[fr][nf0], ah[fr][0], ah[fr][1], ah[fr][2], ah[fr][3], bh0, bh1);
                    mma16816(acc[fr][nf1], ah[fr][0], ah[fr][1], ah[fr][2], ah[fr][3], bh2, bh3);
                    mma16816(acc[fr][nf0], ah[fr][0], ah[fr][1], ah[fr][2], ah[fr][3], bl0, bl1);
                    mma16816(acc[fr][nf1], ah[fr][0], ah[fr][1], ah[fr][2], ah[fr][3], bl2, bl3);
                    mma16816(acc[fr][nf0], al[fr][0], al[fr][1], al[fr][2], al[fr][3], bh0, bh1);
                    mma16816(acc[fr][nf1], al[fr][0], al[fr][1], al[fr][2], al[fr][3], bh2, bh3);
                }
            }
        }
    }

    float* __restrict__ xpd = g_xp[d];
#pragma unroll
    for (int nf = 0; nf < 8; nf++) {
        int n0 = nb * 128 + warp_n + nf * 8 + (lane & 3) * 2;
        float bias0 = bi[n0] + bh[n0];
        float bias1 = bi[n0 + 1] + bh[n0 + 1];
        size_t off0 = (size_t)((n0 & 511) * 4 + (n0 >> 9));
        size_t off1 = (size_t)(((n0 + 1) & 511) * 4 + ((n0 + 1) >> 9));
#pragma unroll
        for (int fr = 0; fr < 2; fr++) {
            int m0 = mb * 128 + warp_m + fr * 16 + (lane >> 2);
            xpd[(size_t)m0       * G_ + off0] = acc[fr][nf][0] + bias0;
            xpd[(size_t)m0       * G_ + off1] = acc[fr][nf][1] + bias1;
            xpd[(size_t)(m0 + 8) * G_ + off0] = acc[fr][nf][2] + bias0;
            xpd[(size_t)(m0 + 8) * G_ + off1] = acc[fr][nf][3] + bias1;
        }
    }
}

// ---------------- persistent BiLSTM recurrence ----------------
// 128 CTAs (2 dirs x 64 unit-blocks of 8 units), 256 threads, 192 KB smem.
// Per-direction release/acquire barrier (no L1 flush), cp.async h staging,
// pre-barrier prefetch of next-step xp/sentiment.
__global__ __launch_bounds__(256, 1) void lstm_persist(
    const float* __restrict__ sent, float* __restrict__ out)
{
    extern __shared__ float sm[];
    float* h_sm = sm;            // float4[256 kp][32 bp] = 128 KB
    float* w_sm = sm + 32768;    // float [256 kp][8 u_off][8] = 64 KB

    const int blk = blockIdx.x;
    const int d   = blk >> 6;
    const int ub  = blk & 63;
    const int tid = threadIdx.x;
    const int warp = tid >> 5, lane = tid & 31;
    const int u_off = (warp & 1) * 4 + (lane >> 3);
    const int bp    = (warp >> 1) * 8 + (lane & 7);
    const int u  = ub * 8 + u_off;
    const int b0 = bp * 2, b1 = b0 + 1;

    {
        const float4* wp4 = (const float4*)&g_wt2[d][ub][0][0][0];
        float4* ws4 = (float4*)w_sm;
#pragma unroll
        for (int i = 0; i < 16; i++) ws4[i * 256 + tid] = wp4[i * 256 + tid];
    }

    float c0 = 0.0f, c1 = 0.0f;
    const float* __restrict__ xpd = g_xp[d];
    const ulonglong2* __restrict__ wl2 = (const ulonglong2*)w_sm + u_off * 2;
    const ulonglong2* __restrict__ hl2 = (const ulonglong2*)h_sm + bp;
    const uint32_t h_sm_b = sm_u32(h_sm) + tid * 16;
    unsigned int* const barp = &g_barD[d];

    // prefetch step 0 xp/sent
    int t0 = d ? (S_ - 1) : 0;
    float4 xq0 = __ldcs((const float4*)(xpd + ((size_t)b0 * S_ + t0) * G_ + (size_t)u * 4));
    float4 xq1 = __ldcs((const float4*)(xpd + ((size_t)b1 * S_ + t0) * G_ + (size_t)u * 4));
    float st0 = __ldg(sent + b0 * S_ + t0);
    float st1 = __ldg(sent + b1 * S_ + t0);

    for (int s = 0; s < S_; s++) {
        const int t = d ? (S_ - 1 - s) : s;
        const int p = s & 1;

        // stage h_prev via cp.async (L2-direct, no reg round-trip)
        {
            const float4* hp4 = (const float4*)g_h[p][d] + tid;
#pragma unroll
            for (int i = 0; i < 32; i++)
                cp_async16(h_sm_b + (uint32_t)i * 4096, hp4 + i * 256);
            cp_async_wait_all();
        }
        __syncthreads();

        // GEMM: 4 gate-columns x 2 batches, k-paired f32x2
        unsigned long long ai0 = 0, af0 = 0, ag0 = 0, ao0 = 0;
        unsigned long long ai1 = 0, af1 = 0, ag1 = 0, ao1 = 0;
#pragma unroll 8
        for (int kp = 0; kp < 256; kp++) {
            ulonglong2 h2 = hl2[(size_t)kp * 32];
            ulonglong2 wa = wl2[(size_t)kp * 16];
            ulonglong2 wb = wl2[(size_t)kp * 16 + 1];
            fma2(ai0, h2.x, wa.x);
            fma2(af0, h2.x, wa.y);
            fma2(ag0, h2.x, wb.x);
            fma2(ao0, h2.x, wb.y);
            fma2(ai1, h2.y, wa.x);
            fma2(af1, h2.y, wa.y);
            fma2(ag1, h2.y, wb.x);
            fma2(ao1, h2.y, wb.y);
        }

        // pointwise
        float gi0 = red2(ai0) + xq0.x;
        float gf0 = red2(af0) + xq0.y;
        float gg0 = red2(ag0) + xq0.z;
        float go0 = red2(ao0) + xq0.w;
        float i0 = fast_sig(gi0) * st0;
        float f0 = fast_sig(gf0) * (1.0f + st0);
        float o0 = fast_sig(go0);
        c0 = f0 * c0 + i0 * fast_tanh(gg0);
        float h0 = o0 * fast_tanh(c0);

        float gi1 = red2(ai1) + xq1.x;
        float gf1 = red2(af1) + xq1.y;
        float gg1 = red2(ag1) + xq1.z;
        float go1 = red2(ao1) + xq1.w;
        float i1 = fast_sig(gi1) * st1;
        float f1 = fast_sig(gf1) * (1.0f + st1);
        float o1 = fast_sig(go1);
        c1 = f1 * c1 + i1 * fast_tanh(gg1);
        float h1 = o1 * fast_tanh(c1);

        // write h_next (staging layout, L2) + output
        {
            float* hn = g_h[p ^ 1][d];
            int hbase = ((u >> 1) * 32 + bp) * 4 + (u & 1);
            __stcg(hn + hbase,     h0);
            __stcg(hn + hbase + 2, h1);
        }
        __stcs(out + ((size_t)b0 * S_ + t) * (size_t)(2 * H_) + (size_t)d * H_ + u, h0);
        __stcs(out + ((size_t)b1 * S_ + t) * (size_t)(2 * H_) + (size_t)d * H_ + u, h1);

        if (s == S_ - 1) break;

        // prefetch NEXT step xp/sent before the barrier (hides L2 latency)
        const int tn = d ? (S_ - 2 - s) : (s + 1);
        xq0 = __ldcs((const float4*)(xpd + ((size_t)b0 * S_ + tn) * G_ + (size_t)u * 4));
        xq1 = __ldcs((const float4*)(xpd + ((size_t)b1 * S_ + tn) * G_ + (size_t)u * 4));
        st0 = __ldg(sent + b0 * S_ + tn);
        st1 = __ldg(sent + b1 * S_ + tn);

        // per-direction release/acquire grid barrier (no threadfence/IVALL)
        __syncthreads();
        if (tid == 0) {
            bar_release_add(barp);
            const unsigned int target = (unsigned int)(s + 1) * 64u;
            while (bar_acquire_ld(barp) < target) { }
        }
        __syncthreads();
    }
}

// ---------------- launch ----------------
extern "C" void kernel_launch(void* const* d_in, const int* in_sizes, int n_in,
                              void* d_out, int out_size) {
    const float* x    = (const float*)d_in[0];
    const float* sent = (const float*)d_in[1];
    const float* Wi_f = (const float*)d_in[2];
    const float* bi_f = (const float*)d_in[3];
    const float* Wh_f = (const float*)d_in[4];
    const float* bh_f = (const float*)d_in[5];
    const float* Wi_b = (const float*)d_in[6];
    const float* bi_b = (const float*)d_in[7];
    const float* Wh_b = (const float*)d_in[8];
    const float* bh_b = (const float*)d_in[9];
    float* out = (float*)d_out;

    cudaFuncSetAttribute(lstm_persist,
                         cudaFuncAttributeMaxDynamicSharedMemorySize, 196608);
    cudaFuncSetAttribute(proj_mma_kernel,
                         cudaFuncAttributeMaxDynamicSharedMemorySize, 65536);

    // reset barriers, zero h, pack Wh; build bf16 splits
    prep_kernel<<<8192, 256>>>(Wh_f, Wh_b);
    conv_x_kernel<<<(int)(((size_t)M_ * I_ + 255) / 256), 256>>>(x);
    conv_w_kernel<<<(int)((2 * (size_t)I_ * G_ + 255) / 256), 256>>>(Wi_f, Wi_b);

    // tensor-core input projection, both directions
    dim3 pg(16, 256, 2);
    proj_mma_kernel<<<pg, 256, 65536>>>(bi_f, bh_f, bi_b, bh_b);

    // whole recurrence in one persistent launch
    lstm_persist<<<NBLK, 256, 196608>>>(sent, out);
}

// round 14
// speedup vs baseline: 2.2645x; 1.0482x over previous
#include <cuda_runtime.h>
#include <cuda_bf16.h>
#include <cstdint>
#include <cstddef>

#define B_ 64
#define S_ 512
#define I_ 768
#define H_ 512
#define G_ 2048            // 4*H
#define M_ 32768           // B*S
#define NBLK 128

// ---------------- device scratch (no allocations allowed) ----------------
// xp: gate-interleaved input projection [dir][m][u*4+g], g in {i,f,g,o}
__device__ __align__(16) float g_xp[2][(size_t)M_ * G_];        // 512 MB
// bf16 splits of x and Wi
__device__ __align__(16) __nv_bfloat16 g_xh[(size_t)M_ * I_];   // 48 MB
__device__ __align__(16) __nv_bfloat16 g_xl[(size_t)M_ * I_];   // 48 MB
__device__ __align__(16) __nv_bfloat16 g_wh[2][(size_t)I_ * G_];// 6.3 MB
__device__ __align__(16) __nv_bfloat16 g_wl[2][(size_t)I_ * G_];
// Wh packed for the step kernel: [dir][ub][kp][u_off][8]
__device__ __align__(16) float g_wt2[2][64][256][8][8];         // 8 MB
// hidden state ping-pong: [parity][dir] as float4[kp][bp]
__device__ __align__(16) float g_h[2][2][H_ * B_];
// per-direction grid barrier counters (monotonic within one launch)
__device__ unsigned int g_barD[2];

// ---------------- helpers ----------------
__device__ __forceinline__ unsigned long long splat2(float v) {
    unsigned long long r;
    asm("mov.b64 %0, {%1, %1};" : "=l"(r) : "f"(v));
    return r;
}
__device__ __forceinline__ void fma2(unsigned long long& acc,
                                     unsigned long long a, unsigned long long b) {
    asm("fma.rn.f32x2 %0, %1, %2, %0;" : "+l"(acc) : "l"(a), "l"(b));
}
__device__ __forceinline__ float red2(unsigned long long a) {
    float2 v = *(float2*)&a;
    return v.x + v.y;
}
__device__ __forceinline__ float fast_rcp(float x) {
    float r;
    asm("rcp.approx.f32 %0, %1;" : "=f"(r) : "f"(x));
    return r;
}
__device__ __forceinline__ float fast_sig(float x) {
    return fast_rcp(1.0f + __expf(-x));
}
__device__ __forceinline__ float fast_tanh(float x) {
    return 1.0f - 2.0f * fast_rcp(1.0f + __expf(2.0f * x));
}
__device__ __forceinline__ uint32_t sm_u32(const void* p) {
    return (uint32_t)__cvta_generic_to_shared(p);
}
__device__ __forceinline__ void cp_async16(uint32_t smem_addr, const void* gptr) {
    asm volatile("cp.async.cg.shared.global [%0], [%1], 16;"
                 :: "r"(smem_addr), "l"(gptr));
}
__device__ __forceinline__ void cp_async_commit() {
    asm volatile("cp.async.commit_group;" ::: "memory");
}
__device__ __forceinline__ void cp_async_wait1() {
    asm volatile("cp.async.wait_group 1;" ::: "memory");
}
__device__ __forceinline__ void cp_async_wait0() {
    asm volatile("cp.async.wait_group 0;" ::: "memory");
}
__device__ __forceinline__ void bar_release_add(unsigned int* p) {
    asm volatile("red.release.gpu.global.add.u32 [%0], 1;" :: "l"(p) : "memory");
}
__device__ __forceinline__ unsigned int bar_acquire_ld(const unsigned int* p) {
    unsigned int v;
    asm volatile("ld.acquire.gpu.global.u32 %0, [%1];" : "=r"(v) : "l"(p) : "memory");
    return v;
}
__device__ __forceinline__ void ldsm4(uint32_t addr, uint32_t& r0, uint32_t& r1,
                                      uint32_t& r2, uint32_t& r3) {
    asm volatile("ldmatrix.sync.aligned.m8n8.x4.shared.b16 {%0,%1,%2,%3}, [%4];"
                 : "=r"(r0), "=r"(r1), "=r"(r2), "=r"(r3) : "r"(addr));
}
__device__ __forceinline__ void ldsm4t(uint32_t addr, uint32_t& r0, uint32_t& r1,
                                       uint32_t& r2, uint32_t& r3) {
    asm volatile("ldmatrix.sync.aligned.m8n8.x4.trans.shared.b16 {%0,%1,%2,%3}, [%4];"
                 : "=r"(r0), "=r"(r1), "=r"(r2), "=r"(r3) : "r"(addr));
}
__device__ __forceinline__ void mma16816(float* d, uint32_t a0, uint32_t a1,
                                         uint32_t a2, uint32_t a3,
                                         uint32_t b0, uint32_t b1) {
    asm volatile(
        "mma.sync.aligned.m16n8k16.row.col.f32.bf16.bf16.f32 "
        "{%0,%1,%2,%3}, {%4,%5,%6,%7}, {%8,%9}, {%0,%1,%2,%3};"
        : "+f"(d[0]), "+f"(d[1]), "+f"(d[2]), "+f"(d[3])
        : "r"(a0), "r"(a1), "r"(a2), "r"(a3), "r"(b0), "r"(b1));
}

// ---------------- prep: reset barriers, zero h, build packed Wh ----------------
__global__ void prep_kernel(const float* __restrict__ Wh_f,
                            const float* __restrict__ Wh_b) {
    int idx = blockIdx.x * blockDim.x + threadIdx.x;
    if (idx < 2 * H_ * G_) {
        int d = idx >> 20;
        int r = idx & 0xFFFFF;
        int k = r >> 11;
        int n = r & 2047;
        int g = n >> 9;
        int u = n & 511;
        const float* __restrict__ Wh = d ? Wh_b : Wh_f;
        size_t dst = ((((size_t)d * 64 + (u >> 3)) * 256 + (k >> 1)) * 8
                      + (u & 7)) * 8 + (g << 1) + (k & 1);
        ((float*)g_wt2)[dst] = Wh[(size_t)k * G_ + n];
    }
    if (idx < 2 * 2 * H_ * B_) {
        ((float*)g_h)[idx] = 0.0f;
    }
    if (idx == 0) { g_barD[0] = 0u; g_barD[1] = 0u; }
}

// no-op marker so lstm_persist is the 6th launch (ncu -s 5 -c 1 captures it)
__global__ void marker_kernel() {}

// ---------------- bf16 split conversions ----------------
__global__ void conv_x_kernel(const float* __restrict__ x) {
    size_t idx = (size_t)blockIdx.x * blockDim.x + threadIdx.x;
    if (idx < (size_t)M_ * I_) {
        float v = x[idx];
        __nv_bfloat16 h = __float2bfloat16(v);
        g_xh[idx] = h;
        g_xl[idx] = __float2bfloat16(v - __bfloat162float(h));
    }
}
__global__ void conv_w_kernel(const float* __restrict__ Wi_f,
                              const float* __restrict__ Wi_b) {
    size_t idx = (size_t)blockIdx.x * blockDim.x + threadIdx.x;
    const size_t n1 = (size_t)I_ * G_;
    if (idx < 2 * n1) {
        int d = idx >= n1;
        size_t r = d ? idx - n1 : idx;
        float v = (d ? Wi_b : Wi_f)[r];
        __nv_bfloat16 h = __float2bfloat16(v);
        g_wh[d][r] = h;
        g_wl[d][r] = __float2bfloat16(v - __bfloat162float(h));
    }
}

// ---------------- tensor-core projection: xp = x@Wi + bi + bh (3-term bf16) ----------------
#define PA_HI 0
#define PA_LO 16384
#define PB_HI 32768
#define PB_LO 49152

__global__ __launch_bounds__(256) void proj_mma_kernel(
    const float* __restrict__ bi_f, const float* __restrict__ bh_f,
    const float* __restrict__ bi_b, const float* __restrict__ bh_b)
{
    extern __shared__ char smem[];
    const uint32_t smem_b = sm_u32(smem);

    const int d  = blockIdx.z;
    const int mb = blockIdx.y;
    const int nb = blockIdx.x;
    const int tid = threadIdx.x;
    const int warp = tid >> 5, lane = tid & 31;
    const int warp_m = (warp >> 1) * 32;
    const int warp_n = (warp & 1) * 64;

    const __nv_bfloat16* __restrict__ wh = g_wh[d];
    const __nv_bfloat16* __restrict__ wl = g_wl[d];
    const float* __restrict__ bi = d ? bi_b : bi_f;
    const float* __restrict__ bh = d ? bh_b : bh_f;

    float acc[2][8][4];
#pragma unroll
    for (int fr = 0; fr < 2; fr++)
#pragma unroll
        for (int nf = 0; nf < 8; nf++)
#pragma unroll
            for (int r = 0; r < 4; r++) acc[fr][nf][r] = 0.0f;

    for (int kc = 0; kc < I_; kc += 64) {
        if (kc) __syncthreads();
#pragma unroll
        for (int i = 0; i < 4; i++) {
            int id = i * 256 + tid;
            int row = id >> 3, c = id & 7;
            size_t ga = (size_t)(mb * 128 + row) * I_ + kc + c * 8;
            int phys = row * 8 + (c ^ (row & 7));
            *((uint4*)(smem + PA_HI) + phys) = *(const uint4*)(g_xh + ga);
            *((uint4*)(smem + PA_LO) + phys) = *(const uint4*)(g_xl + ga);
        }
#pragma unroll
        for (int i = 0; i < 4; i++) {
            int id = i * 256 + tid;
            int row = id >> 4, c = id & 15;
            size_t gb = (size_t)(kc + row) * G_ + nb * 128 + c * 8;
            int phys = row * 16 + (c ^ (row & 7));
            *((uint4*)(smem + PB_HI) + phys) = *(const uint4*)(wh + gb);
            *((uint4*)(smem + PB_LO) + phys) = *(const uint4*)(wl + gb);
        }
        __syncthreads();

#pragma unroll
        for (int k16 = 0; k16 < 64; k16 += 16) {
            uint32_t ah[2][4], al[2][4];
#pragma unroll
            for (int fr = 0; fr < 2; fr++) {
                int row = warp_m + fr * 16 + (lane & 15);
                int cb = (k16 >> 3) + (lane >> 4);
                uint32_t off = (uint32_t)(row * 8 + (cb ^ (row & 7))) * 16;
                ldsm4(smem_b + PA_HI + off, ah[fr][0], ah[fr][1], ah[fr][2], ah[fr][3]);
                ldsm4(smem_b + PA_LO + off, al[fr][0], al[fr][1], al[fr][2], al[fr][3]);
            }
#pragma unroll
            for (int ng = 0; ng < 4; ng++) {
                int row = k16 + ((lane >> 3) & 1) * 8 + (lane & 7);
                int c0 = (warp_n >> 3) + ng * 2 + (lane >> 4);
                uint32_t off = (uint32_t)(row * 16 + (c0 ^ (row & 7))) * 16;
                uint32_t bh0, bh1, bh2, bh3, bl0, bl1, bl2, bl3;
                ldsm4t(smem_b + PB_HI + off, bh0, bh1, bh2, bh3);
                ldsm4t(smem_b + PB_LO + off, bl0, bl1, bl2, bl3);
                int nf0 = ng * 2, nf1 = ng * 2 + 1;
#pragma unroll
                for (int fr = 0; fr < 2; fr++) {
                    mma16816(acc[fr][nf0], ah[fr][0], ah[fr][1], ah[fr][2], ah[fr][3], bh0, bh1);
                    mma16816(acc[fr][nf1], ah[fr][0], ah[fr][1], ah[fr][2], ah[fr][3], bh2, bh3);
                    mma16816(acc[fr][nf0], ah[fr][0], ah[fr][1], ah[fr][2], ah[fr][3], bl0, bl1);
                    mma16816(acc[fr][nf1], ah[fr][0], ah[fr][1], ah[fr][2], ah[fr][3], bl2, bl3);
                    mma16816(acc[fr][nf0], al[fr][0], al[fr][1], al[fr][2], al[fr][3], bh0, bh1);
                    mma16816(acc[fr][nf1], al[fr][0], al[fr][1], al[fr][2], al[fr][3], bh2, bh3);
                }
            }
        }
    }

    float* __restrict__ xpd = g_xp[d];
#pragma unroll
    for (int nf = 0; nf < 8; nf++) {
        int n0 = nb * 128 + warp_n + nf * 8 + (lane & 3) * 2;
        float bias0 = bi[n0] + bh[n0];
        float bias1 = bi[n0 + 1] + bh[n0 + 1];
        size_t off0 = (size_t)((n0 & 511) * 4 + (n0 >> 9));
        size_t off1 = (size_t)(((n0 + 1) & 511) * 4 + ((n0 + 1) >> 9));
#pragma unroll
        for (int fr = 0; fr < 2; fr++) {
            int m0 = mb * 128 + warp_m + fr * 16 + (lane >> 2);
            xpd[(size_t)m0       * G_ + off0] = acc[fr][nf][0] + bias0;
            xpd[(size_t)m0       * G_ + off1] = acc[fr][nf][1] + bias1;
            xpd[(size_t)(m0 + 8) * G_ + off0] = acc[fr][nf][2] + bias0;
            xpd[(size_t)(m0 + 8) * G_ + off1] = acc[fr][nf][3] + bias1;
        }
    }
}

// ---------------- persistent BiLSTM recurrence ----------------
// 128 CTAs (2 dirs x 64 unit-blocks of 8 units), 256 threads, 192 KB smem.
// h staging split into two cp.async groups overlapped with the two GEMM halves.
__global__ __launch_bounds__(256, 1) void lstm_persist(
    const float* __restrict__ sent, float* __restrict__ out)
{
    extern __shared__ float sm[];
    float* h_sm = sm;            // float4[256 kp][32 bp] = 128 KB
    float* w_sm = sm + 32768;    // float [256 kp][8 u_off][8] = 64 KB

    const int blk = blockIdx.x;
    const int d   = blk >> 6;
    const int ub  = blk & 63;
    const int tid = threadIdx.x;
    const int warp = tid >> 5, lane = tid & 31;
    const int u_off = (warp & 1) * 4 + (lane >> 3);
    const int bp    = (warp >> 1) * 8 + (lane & 7);
    const int u  = ub * 8 + u_off;
    const int b0 = bp * 2, b1 = b0 + 1;

    {
        const float4* wp4 = (const float4*)&g_wt2[d][ub][0][0][0];
        float4* ws4 = (float4*)w_sm;
#pragma unroll
        for (int i = 0; i < 16; i++) ws4[i * 256 + tid] = wp4[i * 256 + tid];
    }

    float c0 = 0.0f, c1 = 0.0f;
    const float* __restrict__ xpd = g_xp[d];
    const ulonglong2* __restrict__ wl2 = (const ulonglong2*)w_sm + u_off * 2;
    const ulonglong2* __restrict__ hl2 = (const ulonglong2*)h_sm + bp;
    const uint32_t h_sm_b = sm_u32(h_sm) + tid * 16;
    unsigned int* const barp = &g_barD[d];

    // prefetch step 0 xp/sent
    int t0 = d ? (S_ - 1) : 0;
    float4 xq0 = __ldcs((const float4*)(xpd + ((size_t)b0 * S_ + t0) * G_ + (size_t)u * 4));
    float4 xq1 = __ldcs((const float4*)(xpd + ((size_t)b1 * S_ + t0) * G_ + (size_t)u * 4));
    float st0 = __ldg(sent + b0 * S_ + t0);
    float st1 = __ldg(sent + b1 * S_ + t0);

    for (int s = 0; s < S_; s++) {
        const int t = d ? (S_ - 1 - s) : s;
        const int p = s & 1;

        // stage h_prev in two cp.async groups (64 KB each)
        {
            const float4* hp4 = (const float4*)g_h[p][d] + tid;
#pragma unroll
            for (int i = 0; i < 16; i++)
                cp_async16(h_sm_b + (uint32_t)i * 4096, hp4 + i * 256);
            cp_async_commit();
#pragma unroll
            for (int i = 16; i < 32; i++)
                cp_async16(h_sm_b + (uint32_t)i * 4096, hp4 + i * 256);
            cp_async_commit();
        }
        cp_async_wait1();            // first half landed
        __syncthreads();

        // GEMM half 1: kp 0..127 (second 64 KB still in flight)
        unsigned long long ai0 = 0, af0 = 0, ag0 = 0, ao0 = 0;
        unsigned long long ai1 = 0, af1 = 0, ag1 = 0, ao1 = 0;
#pragma unroll 8
        for (int kp = 0; kp < 128; kp++) {
            ulonglong2 h2 = hl2[(size_t)kp * 32];
            ulonglong2 wa = wl2[(size_t)kp * 16];
            ulonglong2 wb = wl2[(size_t)kp * 16 + 1];
            fma2(ai0, h2.x, wa.x);
            fma2(af0, h2.x, wa.y);
            fma2(ag0, h2.x, wb.x);
            fma2(ao0, h2.x, wb.y);
            fma2(ai1, h2.y, wa.x);
            fma2(af1, h2.y, wa.y);
            fma2(ag1, h2.y, wb.x);
            fma2(ao1, h2.y, wb.y);
        }

        cp_async_wait0();            // second half landed
        __syncthreads();

        // GEMM half 2: kp 128..255
#pragma unroll 8
        for (int kp = 128; kp < 256; kp++) {
            ulonglong2 h2 = hl2[(size_t)kp * 32];
            ulonglong2 wa = wl2[(size_t)kp * 16];
            ulonglong2 wb = wl2[(size_t)kp * 16 + 1];
            fma2(ai0, h2.x, wa.x);
            fma2(af0, h2.x, wa.y);
            fma2(ag0, h2.x, wb.x);
            fma2(ao0, h2.x, wb.y);
            fma2(ai1, h2.y, wa.x);
            fma2(af1, h2.y, wa.y);
            fma2(ag1, h2.y, wb.x);
            fma2(ao1, h2.y, wb.y);
        }

        // pointwise
        float gi0 = red2(ai0) + xq0.x;
        float gf0 = red2(af0) + xq0.y;
        float gg0 = red2(ag0) + xq0.z;
        float go0 = red2(ao0) + xq0.w;
        float i0 = fast_sig(gi0) * st0;
        float f0 = fast_sig(gf0) * (1.0f + st0);
        float o0 = fast_sig(go0);
        c0 = f0 * c0 + i0 * fast_tanh(gg0);
        float h0 = o0 * fast_tanh(c0);

        float gi1 = red2(ai1) + xq1.x;
        float gf1 = red2(af1) + xq1.y;
        float gg1 = red2(ag1) + xq1.z;
        float go1 = red2(ao1) + xq1.w;
        float i1 = fast_sig(gi1) * st1;
        float f1 = fast_sig(gf1) * (1.0f + st1);
        float o1 = fast_sig(go1);
        c1 = f1 * c1 + i1 * fast_tanh(gg1);
        float h1 = o1 * fast_tanh(c1);

        // write h_next (staging layout, L2) + output
        {
            float* hn = g_h[p ^ 1][d];
            int hbase = ((u >> 1) * 32 + bp) * 4 + (u & 1);
            __stcg(hn + hbase,     h0);
            __stcg(hn + hbase + 2, h1);
        }
        __stcs(out + ((size_t)b0 * S_ + t) * (size_t)(2 * H_) + (size_t)d * H_ + u, h0);
        __stcs(out + ((size_t)b1 * S_ + t) * (size_t)(2 * H_) + (size_t)d * H_ + u, h1);

        if (s == S_ - 1) break;

        // prefetch NEXT step xp/sent before the barrier (hides L2 latency)
        const int tn = d ? (S_ - 2 - s) : (s + 1);
        xq0 = __ldcs((const float4*)(xpd + ((size_t)b0 * S_ + tn) * G_ + (size_t)u * 4));
        xq1 = __ldcs((const float4*)(xpd + ((size_t)b1 * S_ + tn) * G_ + (size_t)u * 4));
        st0 = __ldg(sent + b0 * S_ + tn);
        st1 = __ldg(sent + b1 * S_ + tn);

        // per-direction release/acquire grid barrier (no threadfence/IVALL)
        __syncthreads();
        if (tid == 0) {
            bar_release_add(barp);
            const unsigned int target = (unsigned int)(s + 1) * 64u;
            while (bar_acquire_ld(barp) < target) { }
        }
        __syncthreads();
    }
}

// ---------------- launch ----------------
extern "C" void kernel_launch(void* const* d_in, const int* in_sizes, int n_in,
                              void* d_out, int out_size) {
    const float* x    = (const float*)d_in[0];
    const float* sent = (const float*)d_in[1];
    const float* Wi_f = (const float*)d_in[2];
    const float* bi_f = (const float*)d_in[3];
    const float* Wh_f = (const float*)d_in[4];
    const float* bh_f = (const float*)d_in[5];
    const float* Wi_b = (const float*)d_in[6];
    const float* bi_b = (const float*)d_in[7];
    const float* Wh_b = (const float*)d_in[8];
    const float* bh_b = (const float*)d_in[9];
    float* out = (float*)d_out;

    cudaFuncSetAttribute(lstm_persist,
                         cudaFuncAttributeMaxDynamicSharedMemorySize, 196608);
    cudaFuncSetAttribute(proj_mma_kernel,
                         cudaFuncAttributeMaxDynamicSharedMemorySize, 65536);

    // launches 1..4
    prep_kernel<<<8192, 256>>>(Wh_f, Wh_b);
    conv_x_kernel<<<(int)(((size_t)M_ * I_ + 255) / 256), 256>>>(x);
    conv_w_kernel<<<(int)((2 * (size_t)I_ * G_ + 255) / 256), 256>>>(Wi_f, Wi_b);
    dim3 pg(16, 256, 2);
    proj_mma_kernel<<<pg, 256, 65536>>>(bi_f, bh_f, bi_b, bh_b);

    // launch 5: no-op marker so lstm_persist is launch #6 (ncu -s 5 -c 1 target)
    marker_kernel<<<1, 32>>>();

    // launch 6: whole recurrence in one persistent kernel
    lstm_persist<<<NBLK, 256, 196608>>>(sent, out);
}